// round 5
// baseline (speedup 1.0000x reference)
#include <cuda_runtime.h>
#include <cuda_bf16.h>

#define D 4096
#define THREADS 256
#define NCTAS 608   // 152 SMs x 4 CTAs: one persistent wave

// Bank swizzle for the single shared remap: phys = i ^ g(i),
//   g: i5 -> b0^b1,  i6 -> b1.   GF(2)-linear.
// Write lanes vary i{2..6}: images {b2,b3,b4, b0+b1, b1} rank 5 -> clean.
// Read  lanes vary i{1..5}: images {b1,b2,b3,b4, b0+b1}  rank 5 -> clean.
__device__ __forceinline__ int gb(int i) {
    return (((i >> 5) & 1) * 3) ^ (((i >> 6) & 1) << 1);
}

// 16-point in-register FWHT (bits 0..3 of reg index), fully unrolled.
__device__ __forceinline__ void fwht16(float r[16]) {
#pragma unroll
    for (int h = 1; h < 16; h <<= 1) {
#pragma unroll
        for (int j = 0; j < 16; j++) {
            if (!(j & h)) {
                float a = r[j];
                float b = r[j | h];
                r[j] = a + b;
                r[j | h] = a - b;
            }
        }
    }
}

__global__ __launch_bounds__(THREADS, 4)
void rht_kernel(const float* __restrict__ x,
                const float* __restrict__ signs,
                float* __restrict__ out,
                int n_rows) {
    __shared__ float s[2][D];

    const int t = threadIdx.x;
    const int lane = t & 31;

    // write base: i = (h<<10)|(t<<2)|j ; g sources i5,i6 come from t<<2
    const int sb1 = (t << 2) ^ gb(t << 2);
    // read/store base: i = (u>>6)<<10 | (u&63)<<1 | (k<<7) | j0
    const int base_out = ((t >> 6) << 10) | ((t & 63) << 1);
    const int sbr = base_out ^ gb(base_out);

    // per-stage butterfly signs for the 5 shfl stages (lane bit m -> i bit 2+m)
    float sg[5];
#pragma unroll
    for (int m = 0; m < 5; m++) sg[m] = ((lane >> m) & 1) ? -1.0f : 1.0f;

    // signs: identical every row -> registers, pre-scaled by D^-1/2 = 1/64
    const float4* __restrict__ sv4 = reinterpret_cast<const float4*>(signs);
    float4 sv[4];
#pragma unroll
    for (int h = 0; h < 4; h++) {
        float4 v = sv4[(h << 8) + t];
        v.x *= 0.015625f; v.y *= 0.015625f; v.z *= 0.015625f; v.w *= 0.015625f;
        sv[h] = v;
    }

    // prefetch first row
    int row = blockIdx.x;
    float4 xa[4];
    {
        const float4* __restrict__ xv4 =
            reinterpret_cast<const float4*>(x + (size_t)row * D);
#pragma unroll
        for (int h = 0; h < 4; h++) xa[h] = xv4[(h << 8) + t];
    }

    int buf = 0;
    while (row < n_rows) {
        float r[16];

        // ---- Pass A (in-reg): bits {0,1,10,11} ----
#pragma unroll
        for (int h = 0; h < 4; h++) {
            r[h * 4 + 0] = xa[h].x * sv[h].x;
            r[h * 4 + 1] = xa[h].y * sv[h].y;
            r[h * 4 + 2] = xa[h].z * sv[h].z;
            r[h * 4 + 3] = xa[h].w * sv[h].w;
        }
        fwht16(r);

        // ---- Pass B (intra-warp shfl): bits {2..6} = lane bits 0..4 ----
#pragma unroll
        for (int m = 0; m < 5; m++) {
            const float sgm = sg[m];
#pragma unroll
            for (int q = 0; q < 16; q++) {
                float p = __shfl_xor_sync(0xffffffffu, r[q], 1 << m);
                r[q] = fmaf(r[q], sgm, p);
            }
        }

        // ---- shared remap: write i = (h<<10)|(t<<2)|j ----
#pragma unroll
        for (int h = 0; h < 4; h++) {
#pragma unroll
            for (int j = 0; j < 4; j++) {
                s[buf][(sb1 ^ j) + (h << 10)] = r[h * 4 + j];
            }
        }

        // prefetch next row: overlaps barrier + pass C
        const int nrow = row + NCTAS;
        {
            const int prow = (nrow < n_rows) ? nrow : row;  // safe clamp
            const float4* __restrict__ xv4 =
                reinterpret_cast<const float4*>(x + (size_t)prow * D);
#pragma unroll
            for (int h = 0; h < 4; h++) xa[h] = xv4[(h << 8) + t];
        }

        __syncthreads();   // the ONLY barrier per row

        // ---- Pass C: read i = base_out | (k<<7) | j0, fwht over bits {7,8,9} ----
        // reg index: bit0 = j0 (i0), bits 1..3 = k (i7,i8,i9)
#pragma unroll
        for (int k = 0; k < 8; k++) {
#pragma unroll
            for (int j0 = 0; j0 < 2; j0++) {
                r[k * 2 + j0] = s[buf][sbr ^ (k << 7) ^ j0];
            }
        }
        // butterflies over reg bits 1,2,3 only
#pragma unroll
        for (int h = 2; h < 16; h <<= 1) {
#pragma unroll
            for (int j = 0; j < 16; j++) {
                if (!(j & h)) {
                    float a = r[j];
                    float b = r[j | h];
                    r[j] = a + b;
                    r[j | h] = a - b;
                }
            }
        }

        // ---- stores: float2 at i = base_out + (k<<7); coalesced ----
        float2* __restrict__ o2 =
            reinterpret_cast<float2*>(out + (size_t)row * D + base_out);
#pragma unroll
        for (int k = 0; k < 8; k++) {
            float2 v;
            v.x = r[k * 2 + 0];
            v.y = r[k * 2 + 1];
            o2[k << 6] = v;   // (k<<7 floats) = (k<<6) float2s
        }

        row = nrow;
        buf ^= 1;
    }
}

extern "C" void kernel_launch(void* const* d_in, const int* in_sizes, int n_in,
                              void* d_out, int out_size) {
    const float* x     = (const float*)d_in[0];
    const float* signs = (const float*)d_in[1];
    float* out = (float*)d_out;

    const int n_rows = in_sizes[0] / D;  // 8192
    const int grid = (n_rows < NCTAS) ? n_rows : NCTAS;
    rht_kernel<<<grid, THREADS>>>(x, signs, out, n_rows);
}

// round 6
// speedup vs baseline: 1.0889x; 1.0889x over previous
#include <cuda_runtime.h>
#include <cuda_bf16.h>

#define D 4096
#define THREADS 256
#define NCTAS 608   // 152 SMs x 4 CTAs: one persistent wave

// Bank swizzle: phys = i ^ g(i), g = (i>>4) & 0x1C   (i6->b2, i7->b3, i8->b4)
// Conflict-free (rank-5 injective bank maps) for:
//   P1 STS.128 (per-phase lanes vary i{2,3,4}, g const within phase)
//   P2 LDS/STS scalar (lanes vary i{0,1}->b0,b1 and i{6,7,8}->b2,b3,b4 via g)
//   P3 LDS scalar (lanes vary i{0..4}->b0..b4 natively; g from k = per-reg const)
// g never touches bits [1:0] => pass-1 float4 groups stay aligned & ordered.
__device__ __forceinline__ int swz(int i) {
    return i ^ ((i >> 4) & 0x1C);
}

// Packed butterfly: (a0,a1),(b0,b1) -> (a+b, a-b) elementwise.
// 2 butterflies in 2 instructions via f32x2 (vs 4 scalar FADD).
__device__ __forceinline__ void bfly2(float& a0, float& a1, float& b0, float& b1) {
    asm("{\n\t"
        ".reg .b32 m;\n\t"
        ".reg .b64 ra, rb, rs, rd, rn;\n\t"
        "mov.b32 m, 0xBF800000;\n\t"          // -1.0f
        "mov.b64 rn, {m, m};\n\t"
        "mov.b64 ra, {%0, %1};\n\t"
        "mov.b64 rb, {%2, %3};\n\t"
        "add.rn.f32x2 rs, ra, rb;\n\t"        // a + b
        "fma.rn.f32x2 rd, rb, rn, ra;\n\t"    // a - b
        "mov.b64 {%0, %1}, rs;\n\t"
        "mov.b64 {%2, %3}, rd;\n\t"
        "}" : "+f"(a0), "+f"(a1), "+f"(b0), "+f"(b1));
}

// Packed multiply: (a0,a1) *= (s0,s1)
__device__ __forceinline__ void mul2(float& a0, float& a1, float s0, float s1) {
    asm("{\n\t"
        ".reg .b64 ra, rs, rm;\n\t"
        "mov.b64 ra, {%0, %1};\n\t"
        "mov.b64 rs, {%2, %3};\n\t"
        "mul.rn.f32x2 rm, ra, rs;\n\t"
        "mov.b64 {%0, %1}, rm;\n\t"
        "}" : "+f"(a0), "+f"(a1) : "f"(s0), "f"(s1));
}

// 16-point FWHT: stages over reg bits 1..3 packed (pairs along bit 0),
// stage over bit 0 scalar. Stages commute, so order is free.
__device__ __forceinline__ void fwht16p(float r[16]) {
#pragma unroll
    for (int hp = 1; hp < 8; hp <<= 1) {      // reg bits 1,2,3
#pragma unroll
        for (int m = 0; m < 8; m++) {
            if (!(m & hp)) {
                bfly2(r[2 * m], r[2 * m + 1],
                      r[2 * (m | hp)], r[2 * (m | hp) + 1]);
            }
        }
    }
#pragma unroll
    for (int m = 0; m < 8; m++) {             // reg bit 0 (within pack)
        float a = r[2 * m], b = r[2 * m + 1];
        r[2 * m]     = a + b;
        r[2 * m + 1] = a - b;
    }
}

__global__ __launch_bounds__(THREADS, 4)
void rht_kernel(const float* __restrict__ x,
                const float* __restrict__ signs,
                float* __restrict__ out,
                int n_rows) {
    __shared__ float s[2][D];

    const int t = threadIdx.x;

    // pass-1 write: float4 index = (t ^ ((t>>4)&7)) + (h<<8)
    const int f4w = t ^ ((t >> 4) & 7);
    // pass-2 base: i = ((t>>2)<<6) | (t&3)
    const int base2 = ((t >> 2) << 6) | (t & 3);
    const int sb2   = swz(base2);
    // pass-3 base: i = ((t>>6)<<10) | (t&63)   (bits 6..9 zero -> swz = id)
    const int base3 = ((t >> 6) << 10) | (t & 63);

    // signs: row-invariant -> registers, pre-scaled by D^-1/2 = 1/64
    const float4* __restrict__ sv4 = reinterpret_cast<const float4*>(signs);
    float4 sv[4];
#pragma unroll
    for (int h = 0; h < 4; h++) {
        float4 v = sv4[(h << 8) + t];
        v.x *= 0.015625f; v.y *= 0.015625f; v.z *= 0.015625f; v.w *= 0.015625f;
        sv[h] = v;
    }

    // prefetch first row
    int row = blockIdx.x;
    float4 xa[4];
    {
        const float4* __restrict__ xv4 =
            reinterpret_cast<const float4*>(x + (size_t)row * D);
#pragma unroll
        for (int h = 0; h < 4; h++) xa[h] = xv4[(h << 8) + t];
    }

    int buf = 0;
    while (row < n_rows) {
        float r[16];

        // ---- Pass A: bits {0,1,10,11} (reg: j->i{0,1}, h->i{10,11}) ----
#pragma unroll
        for (int h = 0; h < 4; h++) {
            r[h * 4 + 0] = xa[h].x; r[h * 4 + 1] = xa[h].y;
            r[h * 4 + 2] = xa[h].z; r[h * 4 + 3] = xa[h].w;
            mul2(r[h * 4 + 0], r[h * 4 + 1], sv[h].x, sv[h].y);
            mul2(r[h * 4 + 2], r[h * 4 + 3], sv[h].z, sv[h].w);
        }
        fwht16p(r);

        // ---- remap 1: 4x STS.128 at i = (h<<10)|(t<<2)|j ----
        {
            float4* __restrict__ s4 = reinterpret_cast<float4*>(s[buf]);
#pragma unroll
            for (int h = 0; h < 4; h++) {
                s4[(h << 8) + f4w] =
                    make_float4(r[h * 4 + 0], r[h * 4 + 1],
                                r[h * 4 + 2], r[h * 4 + 3]);
            }
        }

        // ---- prefetch next row (overlaps barrier + passes B/C) ----
        const int nrow = row + NCTAS;
        {
            const int prow = (nrow < n_rows) ? nrow : row;  // safe clamp
            const float4* __restrict__ xv4 =
                reinterpret_cast<const float4*>(x + (size_t)prow * D);
#pragma unroll
            for (int h = 0; h < 4; h++) xa[h] = xv4[(h << 8) + t];
        }

        __syncthreads();

        // ---- Pass B: bits {2,3,4,5} (reg k -> i{2..5}) ----
#pragma unroll
        for (int k = 0; k < 16; k++) {
            r[k] = s[buf][sb2 ^ (k << 2)];
        }
        fwht16p(r);
#pragma unroll
        for (int k = 0; k < 16; k++) {
            s[buf][sb2 ^ (k << 2)] = r[k];
        }
        __syncthreads();

        // ---- Pass C: bits {6,7,8,9} (reg k -> i{6..9}) ----
#pragma unroll
        for (int k = 0; k < 16; k++) {
            r[k] = s[buf][base3 ^ (k << 6) ^ ((k & 7) << 2)];
        }
        fwht16p(r);

        // ---- coalesced scalar stores at logical i = base3 + k*64 ----
        float* __restrict__ orow = out + (size_t)row * D;
#pragma unroll
        for (int k = 0; k < 16; k++) {
            orow[base3 + (k << 6)] = r[k];
        }

        row = nrow;
        buf ^= 1;
    }
}

extern "C" void kernel_launch(void* const* d_in, const int* in_sizes, int n_in,
                              void* d_out, int out_size) {
    const float* x     = (const float*)d_in[0];
    const float* signs = (const float*)d_in[1];
    float* out = (float*)d_out;

    const int n_rows = in_sizes[0] / D;  // 8192
    const int grid = (n_rows < NCTAS) ? n_rows : NCTAS;
    rht_kernel<<<grid, THREADS>>>(x, signs, out, n_rows);
}